// round 6
// baseline (speedup 1.0000x reference)
#include <cuda_runtime.h>
#include <math.h>
#include <float.h>

// Shapes: B=8, N=512, T=64, D=128, E=32, M=3, k_top=25
#define KTOP 25

// ---------------- scratch (__device__ globals; allocation is forbidden) ----------------
__device__ float g_uv[2 * 384];            // u = W_ih@proj_W ; v = W_ih@proj_b + b_ih
__device__ float g_qn[3 * 32 * 128];       // normalized queries [m][e][d]
__device__ float g_s[4096 * 64];           // scalar input s(i,t) after scrambled reshape
__device__ float g_H[4096 * 128];          // final GRU hidden state [b*512+n][d]
__device__ float g_hw[4096];               // h . out_W
__device__ float g_zpw[4096];              // prior @ hw
__device__ float g_probs[8 * 3];
__device__ float g_scores[8 * 3 * 32 * 512];   // [b][m][e][n]
__device__ float g_Hmix[8 * 32 * 512];         // [b][e][n]

// ---------------- helpers ----------------
__device__ __forceinline__ unsigned long long pk2(float lo, float hi) {
    unsigned long long r;
    asm("mov.b64 %0,{%1,%2};" : "=l"(r) : "f"(lo), "f"(hi));
    return r;
}
__device__ __forceinline__ void upk2(unsigned long long v, float& lo, float& hi) {
    asm("mov.b64 {%0,%1},%2;" : "=f"(lo), "=f"(hi) : "l"(v));
}
#define FMA2(acc, a, b) asm("fma.rn.f32x2 %0,%1,%2,%0;" : "+l"(acc) : "l"(a), "l"(b))

__device__ __forceinline__ float sigm(float x) { return 1.0f / (1.0f + __expf(-x)); }
__device__ __forceinline__ float tanh_f(float x) {
    float t = __expf(-2.0f * x);
    return (1.0f - t) / (1.0f + t);
}
__device__ __forceinline__ float warp_sum(float v) {
#pragma unroll
    for (int off = 16; off; off >>= 1) v += __shfl_xor_sync(0xFFFFFFFFu, v, off);
    return v;
}

// ---------------- K0: prep (u, v, normalized queries) ----------------
__global__ void k_prep(const float* __restrict__ Wih, const float* __restrict__ pW,
                       const float* __restrict__ pb, const float* __restrict__ bih,
                       const float* __restrict__ q) {
    int tid = threadIdx.x;
    if (tid < 384) {
        float su = 0.f, sv = 0.f;
        for (int d = 0; d < 128; d++) {
            float w = Wih[tid * 128 + d];
            su = fmaf(w, pW[d], su);
            sv = fmaf(w, pb[d], sv);
        }
        g_uv[tid] = su;
        g_uv[384 + tid] = sv + bih[tid];
    }
    if (tid < 96) {  // rows of queries: m*32+e
        float ss = 0.f;
        for (int d = 0; d < 128; d++) { float v = q[tid * 128 + d]; ss = fmaf(v, v, ss); }
        float inv = 1.0f / fmaxf(sqrtf(ss), 1e-12f);
        for (int d = 0; d < 128; d++) g_qn[tid * 128 + d] = q[tid * 128 + d] * inv;
    }
}

// ---------------- K1: build s(i,t) from the scrambled [B,T,N,D] reshape + zero Hmix ----
// seq flat elem e = i*64+t maps to hp elem: b=e>>15, t_orig=(e>>9)&63, n_orig=e&511.
// x is [B,N,T,1].
__global__ void k_sfill(const float* __restrict__ x) {
    int e = blockIdx.x * blockDim.x + threadIdx.x;  // 262144 threads
    int b = e >> 15;
    int n_o = e & 511;
    int t_o = (e >> 9) & 63;
    g_s[e] = x[b * 32768 + n_o * 64 + t_o];
    if (e < 8 * 32 * 512) g_Hmix[e] = 0.f;
}

// ---------------- K2: GRU (hot kernel) ----------------
// 128 CTAs x 256 threads, 32 sequences per CTA. W_hh persistent in SMEM as
// Wt[k][d*3+g]. Packed f32x2 FMA inner product.
#define WSTR 388  // padded row stride in floats (1552B, 16B-aligned rows)

__global__ __launch_bounds__(256) void k_gru(const float* __restrict__ Whh,
                                             const float* __restrict__ bhh) {
    extern __shared__ float sm[];
    float* Wt = sm;                    // 128*388
    float* hb = sm + 128 * WSTR;       // h[d][seq], stride 32
    float* ssh = hb + 128 * 32;        // s staged [t][seq]

    const int tid = threadIdx.x;
    const int w = tid >> 5, lane = tid & 31;
    const int sg = lane & 7, dg = lane >> 3;
    const int dbase = (w * 4 + dg) * 4;   // 0..124
    const int i0 = blockIdx.x * 32;

    // stage W_hh transposed + gate-interleaved: Wt[k][d*3+g] = W_hh[g*128+d][k]
    for (int idx = tid; idx < 384 * 128; idx += 256) {
        int o = idx >> 7, k = idx & 127;
        int g = o >> 7, d = o & 127;
        Wt[k * WSTR + d * 3 + g] = Whh[idx];
    }
    for (int idx = tid; idx < 32 * 64; idx += 256) {
        int s = idx >> 6, t = idx & 63;
        ssh[t * 32 + s] = g_s[i0 * 64 + idx];
    }
    for (int idx = tid; idx < 128 * 32; idx += 256) hb[idx] = 0.f;

    float u12[12], v12[12], bh12[12];
#pragma unroll
    for (int l = 0; l < 12; l++) {
        int d = dbase + l / 3, g = l % 3, o = g * 128 + d;
        u12[l] = g_uv[o];
        v12[l] = g_uv[384 + o];
        bh12[l] = bhh[o];
    }
    float hreg[16];
#pragma unroll
    for (int q = 0; q < 16; q++) hreg[q] = 0.f;
    __syncthreads();

    const ulonglong2* wbase = (const ulonglong2*)(Wt + dbase * 3);  // 48B offset, aligned

    for (int t = 0; t < 64; t++) {
        unsigned long long acc[24];
#pragma unroll
        for (int q = 0; q < 24; q++) acc[q] = 0ULL;

        float sv[4];
#pragma unroll
        for (int j = 0; j < 4; j++) sv[j] = ssh[t * 32 + sg * 4 + j];

        const float* hp = hb + sg * 4;
        const ulonglong2* wp = wbase;
#pragma unroll 4
        for (int k = 0; k < 128; k++) {
            unsigned long long a2[4];
#pragma unroll
            for (int j = 0; j < 4; j++) {
                float hv = hp[k * 32 + j];
                a2[j] = pk2(hv, hv);
            }
            ulonglong2 b0 = wp[0], b1 = wp[1], b2 = wp[2];
            unsigned long long bb[6] = {b0.x, b0.y, b1.x, b1.y, b2.x, b2.y};
#pragma unroll
            for (int j = 0; j < 4; j++)
#pragma unroll
                for (int p = 0; p < 6; p++) FMA2(acc[j * 6 + p], a2[j], bb[p]);
            wp += WSTR / 4;
        }

        float hnew[16];
#pragma unroll
        for (int j = 0; j < 4; j++) {
            float gh[12];
#pragma unroll
            for (int p = 0; p < 6; p++) upk2(acc[j * 6 + p], gh[2 * p], gh[2 * p + 1]);
            float s = sv[j];
#pragma unroll
            for (int dd = 0; dd < 4; dd++) {
                int l = dd * 3;
                float gr = gh[l + 0] + bh12[l + 0] + fmaf(s, u12[l + 0], v12[l + 0]);
                float gz = gh[l + 1] + bh12[l + 1] + fmaf(s, u12[l + 1], v12[l + 1]);
                float hn = gh[l + 2] + bh12[l + 2];           // gh_n incl. b_hh
                float gn = fmaf(s, u12[l + 2], v12[l + 2]);   // gi_n
                float r = sigm(gr), z = sigm(gz);
                float ng = tanh_f(fmaf(r, hn, gn));
                float ho = hreg[j * 4 + dd];
                hnew[j * 4 + dd] = fmaf(z, ho - ng, ng);      // (1-z)*ng + z*h
            }
        }
        __syncthreads();
#pragma unroll
        for (int j = 0; j < 4; j++)
#pragma unroll
            for (int dd = 0; dd < 4; dd++) {
                float v = hnew[j * 4 + dd];
                hb[(dbase + dd) * 32 + sg * 4 + j] = v;
                hreg[j * 4 + dd] = v;
            }
        __syncthreads();
    }

    for (int idx = tid; idx < 4096; idx += 256) {
        int s = idx >> 7, d = idx & 127;
        g_H[(i0 + s) * 128 + d] = hb[d * 32 + s];
    }
}

// ---------------- K3: hw = h.out_W, router stats + probs ----------------
__global__ void k_stats(const float* __restrict__ outW, const float* __restrict__ rW,
                        const float* __restrict__ rb, float* __restrict__ dout) {
    int b = blockIdx.x;
    int tid = threadIdx.x, w = tid >> 5, lane = tid & 31;
    __shared__ float mean_s[128], sd_s[128], part[256], lg[3];

    float4 ow = ((const float4*)outW)[lane];
    for (int n = w; n < 512; n += 8) {
        float4 hv = ((const float4*)(g_H + (b * 512 + n) * 128))[lane];
        float acc = hv.x * ow.x + hv.y * ow.y + hv.z * ow.z + hv.w * ow.w;
        acc = warp_sum(acc);
        if (lane == 0) g_hw[b * 512 + n] = acc;
    }

    int d = tid & 127, half = tid >> 7;
    float s0 = 0.f;
    for (int n = half * 256; n < half * 256 + 256; n++) s0 += g_H[(b * 512 + n) * 128 + d];
    part[tid] = s0;
    __syncthreads();
    if (tid < 128) mean_s[tid] = (part[tid] + part[tid + 128]) * (1.0f / 512.0f);
    __syncthreads();
    float mu = mean_s[d];
    float s1 = 0.f;
    for (int n = half * 256; n < half * 256 + 256; n++) {
        float v = g_H[(b * 512 + n) * 128 + d] - mu;
        s1 = fmaf(v, v, s1);
    }
    part[tid] = s1;
    __syncthreads();
    if (tid < 128) sd_s[tid] = sqrtf((part[tid] + part[tid + 128]) * (1.0f / 511.0f));
    __syncthreads();

    if (tid < 3) {
        float a = rb[tid];
        for (int k = 0; k < 128; k++) a = fmaf(mean_s[k], rW[tid * 256 + k], a);
        for (int k = 0; k < 128; k++) a = fmaf(sd_s[k], rW[tid * 256 + 128 + k], a);
        lg[tid] = a;
    }
    __syncthreads();
    if (tid == 0) {
        float mx = fmaxf(lg[0], fmaxf(lg[1], lg[2]));
        float e0 = __expf(lg[0] - mx), e1 = __expf(lg[1] - mx), e2 = __expf(lg[2] - mx);
        float inv = 1.0f / (e0 + e1 + e2);
        g_probs[b * 3 + 0] = e0 * inv;
        g_probs[b * 3 + 1] = e1 * inv;
        g_probs[b * 3 + 2] = e2 * inv;
        dout[4096 + b * 3 + 0] = e0 * inv;
        dout[4096 + b * 3 + 1] = e1 * inv;
        dout[4096 + b * 3 + 2] = e2 * inv;
    }
}

// ---------------- K_prior: zpw[b,n] = sum_j prior[n,j]*hw[b,j] ----------------
__global__ void k_prior(const float* __restrict__ prior) {
    __shared__ float prow[512];
    __shared__ float red[8][8];  // [warp][b]
    int n = blockIdx.x, tid = threadIdx.x, w = tid >> 5, lane = tid & 31;
    for (int j = tid; j < 512; j += 256) prow[j] = prior[n * 512 + j];
    __syncthreads();
    int j0 = tid * 2;
    float p0 = prow[j0], p1 = prow[j0 + 1];
#pragma unroll
    for (int b = 0; b < 8; b++) {
        float acc = p0 * g_hw[b * 512 + j0] + p1 * g_hw[b * 512 + j0 + 1];
        acc = warp_sum(acc);
        if (lane == 0) red[w][b] = acc;
    }
    __syncthreads();
    if (tid < 8) {
        float s = 0.f;
#pragma unroll
        for (int ww = 0; ww < 8; ww++) s += red[ww][tid];
        g_zpw[tid * 512 + n] = s;
    }
}

// ---------------- K4: scores[b,m,e,n] = norm(h@spW[m]^T + spb[m]) . qn[m,e] --------
// grid = B*M*16 blocks; each block: one (b,m), 32 n.
__global__ __launch_bounds__(256) void k_scores(const float* __restrict__ spW,
                                                const float* __restrict__ spb) {
    extern __shared__ float sm4[];
    float* W_s = sm4;                    // [128][129]
    float* qn_s = W_s + 128 * 129;       // [k][e] : 128*32
    float* h_s = qn_s + 128 * 32;        // [32][128]
    float* sb_s = h_s + 32 * 128;        // [128]
    float* hs_s = sb_s + 128;            // [8 warps][128]

    int bx = blockIdx.x;
    int b = bx / 48, rem = bx % 48;
    int m = rem / 16, n0 = (rem % 16) * 32;
    int tid = threadIdx.x, w = tid >> 5, lane = tid & 31;

    for (int idx = tid; idx < 16384; idx += 256) {
        int k = idx >> 7, d = idx & 127;
        W_s[k * 129 + d] = spW[m * 16384 + idx];
    }
    for (int idx = tid; idx < 4096; idx += 256) {
        int e = idx >> 7, d = idx & 127;
        qn_s[d * 32 + e] = g_qn[m * 4096 + idx];
    }
    for (int idx = tid; idx < 32 * 128; idx += 256)
        h_s[idx] = g_H[(b * 512 + n0) * 128 + idx];
    if (tid < 128) sb_s[tid] = spb[m * 128 + tid];
    __syncthreads();

    for (int nn = w; nn < 32; nn += 8) {
        const float* hrow = h_s + nn * 128;
        float hsk[4];
#pragma unroll
        for (int q = 0; q < 4; q++) hsk[q] = sb_s[lane + 32 * q];
        for (int d = 0; d < 128; d++) {
            float hv = hrow[d];
#pragma unroll
            for (int q = 0; q < 4; q++)
                hsk[q] = fmaf(W_s[(lane + 32 * q) * 129 + d], hv, hsk[q]);
        }
        float sq = hsk[0] * hsk[0] + hsk[1] * hsk[1] + hsk[2] * hsk[2] + hsk[3] * hsk[3];
        sq = warp_sum(sq);
        float inv = 1.0f / fmaxf(sqrtf(sq), 1e-12f);
#pragma unroll
        for (int q = 0; q < 4; q++) hs_s[w * 128 + lane + 32 * q] = hsk[q] * inv;
        __syncwarp();

        float acc = 0.f;
        for (int k = 0; k < 128; k++)
            acc = fmaf(hs_s[w * 128 + k], qn_s[k * 32 + lane], acc);
        g_scores[((b * 3 + m) * 32 + lane) * 512 + n0 + nn] = acc;
        __syncwarp();
    }
}

// ---------------- K5: top-25 over n + softmax(T=0.7) + Hmix accumulation ----------
__global__ void k_topk() {
    int tid = threadIdx.x, w = tid >> 5, lane = tid & 31;
    int row = blockIdx.x * 8 + w;         // 768 rows = [b][m][e]
    int b = row / 96, m = (row / 32) % 3, e = row % 32;
    const float* sc = g_scores + row * 512;

    float v[16];
#pragma unroll
    for (int j = 0; j < 16; j++) v[j] = sc[lane + j * 32];

    float topv[KTOP];
    int topi[KTOP];
    for (int it = 0; it < KTOP; it++) {
        float bv = -FLT_MAX;
        int bi = 0x7FFFFFFF;
#pragma unroll
        for (int j = 0; j < 16; j++) {
            if (v[j] > bv) { bv = v[j]; bi = lane + j * 32; }
        }
#pragma unroll
        for (int off = 16; off; off >>= 1) {
            float ov = __shfl_xor_sync(0xFFFFFFFFu, bv, off);
            int oi = __shfl_xor_sync(0xFFFFFFFFu, bi, off);
            if (ov > bv || (ov == bv && oi < bi)) { bv = ov; bi = oi; }
        }
        topv[it] = bv;
        topi[it] = bi;
#pragma unroll
        for (int j = 0; j < 16; j++)
            if (lane + j * 32 == bi) v[j] = -FLT_MAX;
    }

    if (lane == 0) {
        float vmax = topv[0];
        float ssum = 0.f;
        float wexp[KTOP];
        const float itau = 1.0f / 0.7f;
        for (int i = 0; i < KTOP; i++) {
            wexp[i] = __expf((topv[i] - vmax) * itau);
            ssum += wexp[i];
        }
        float pm = g_probs[b * 3 + m] / ssum;
        float* hm = g_Hmix + (b * 32 + e) * 512;
        for (int i = 0; i < KTOP; i++) atomicAdd(&hm[topi[i]], pm * wexp[i]);
    }
}

// ---------------- K6: ew = Hmix@hw ; out = a*zpw + (1-a)*Hmix^T@ew + out_b --------
__global__ void k_final(const float* __restrict__ plog, const float* __restrict__ outb,
                        float* __restrict__ dout) {
    int b = blockIdx.x, tid = threadIdx.x, w = tid >> 5, lane = tid & 31;
    __shared__ float hwsm[512], ewsm[32];
    for (int j = tid; j < 512; j += 256) hwsm[j] = g_hw[b * 512 + j];
    __syncthreads();
#pragma unroll
    for (int ei = 0; ei < 4; ei++) {
        int e = w + ei * 8;
        float acc = 0.f;
        const float* hm = g_Hmix + (b * 32 + e) * 512;
        for (int n = lane; n < 512; n += 32) acc = fmaf(hm[n], hwsm[n], acc);
        acc = warp_sum(acc);
        if (lane == 0) ewsm[e] = acc;
    }
    __syncthreads();
    float alpha = sigm(plog[0]);
    float ob = outb[0];
    for (int n = tid; n < 512; n += 256) {
        float acc = 0.f;
#pragma unroll 8
        for (int e = 0; e < 32; e++)
            acc = fmaf(g_Hmix[(b * 32 + e) * 512 + n], ewsm[e], acc);
        dout[b * 512 + n] = fmaf(alpha, g_zpw[b * 512 + n] - acc, acc) + ob;
    }
}

// ---------------- launch ----------------
extern "C" void kernel_launch(void* const* d_in, const int* in_sizes, int n_in,
                              void* d_out, int out_size) {
    const float* x     = (const float*)d_in[0];
    const float* prior = (const float*)d_in[1];
    const float* pW    = (const float*)d_in[2];
    const float* pb    = (const float*)d_in[3];
    const float* Wih   = (const float*)d_in[4];
    const float* Whh   = (const float*)d_in[5];
    const float* bih   = (const float*)d_in[6];
    const float* bhh   = (const float*)d_in[7];
    const float* spW   = (const float*)d_in[8];
    const float* spb   = (const float*)d_in[9];
    const float* rW    = (const float*)d_in[10];
    const float* rb    = (const float*)d_in[11];
    const float* outW  = (const float*)d_in[12];
    const float* outb  = (const float*)d_in[13];
    const float* plog  = (const float*)d_in[14];
    const float* q     = (const float*)d_in[15];
    float* dout = (float*)d_out;

    const int smem_gru = (128 * WSTR + 128 * 32 + 32 * 64) * (int)sizeof(float);   // 223232 B
    const int smem_sc  = (128 * 129 + 128 * 32 + 32 * 128 + 128 + 8 * 128) * (int)sizeof(float);
    cudaFuncSetAttribute(k_gru, cudaFuncAttributeMaxDynamicSharedMemorySize, smem_gru);
    cudaFuncSetAttribute(k_scores, cudaFuncAttributeMaxDynamicSharedMemorySize, smem_sc);

    k_prep<<<1, 384>>>(Wih, pW, pb, bih, q);
    k_sfill<<<1024, 256>>>(x);
    k_gru<<<128, 256, smem_gru>>>(Whh, bhh);
    k_stats<<<8, 256>>>(outW, rW, rb, dout);
    k_prior<<<512, 256>>>(prior);
    k_scores<<<384, 256, smem_sc>>>(spW, spb);
    k_topk<<<96, 256>>>();
    k_final<<<8, 256>>>(plog, outb, dout);
}

// round 10
// speedup vs baseline: 1.0012x; 1.0012x over previous
#include <cuda_runtime.h>
#include <math.h>
#include <float.h>

// Shapes: B=8, N=512, T=64, D=128, E=32, M=3, k_top=25
#define KTOP 25

// ---------------- scratch (__device__ globals; allocation is forbidden) ----------------
__device__ float g_uv[2 * 384];            // u = W_ih@proj_W ; v = W_ih@proj_b + b_ih
__device__ float g_qn[3 * 32 * 128];       // normalized queries [m][e][d]
__device__ float g_s[4096 * 64];           // scalar input s(i,t) after scrambled reshape
__device__ float g_H[4096 * 128];          // final GRU hidden state [b*512+n][d]
__device__ float g_hw[4096];               // h . out_W
__device__ float g_zpw[4096];              // prior @ hw
__device__ float g_probs[8 * 3];
__device__ float g_scores[8 * 3 * 32 * 512];   // [b][m][e][n]
__device__ float g_Hmix[8 * 32 * 512];         // [b][e][n]

// ---------------- helpers ----------------
__device__ __forceinline__ unsigned long long pk2(float lo, float hi) {
    unsigned long long r;
    asm("mov.b64 %0,{%1,%2};" : "=l"(r) : "f"(lo), "f"(hi));
    return r;
}
__device__ __forceinline__ void upk2(unsigned long long v, float& lo, float& hi) {
    asm("mov.b64 {%0,%1},%2;" : "=f"(lo), "=f"(hi) : "l"(v));
}
#define FMA2(acc, a, b) asm("fma.rn.f32x2 %0,%1,%2,%0;" : "+l"(acc) : "l"(a), "l"(b))

__device__ __forceinline__ float sigm(float x) { return 1.0f / (1.0f + __expf(-x)); }
__device__ __forceinline__ float tanh_f(float x) {
    float t = __expf(-2.0f * x);
    return (1.0f - t) / (1.0f + t);
}
__device__ __forceinline__ float warp_sum(float v) {
#pragma unroll
    for (int off = 16; off; off >>= 1) v += __shfl_xor_sync(0xFFFFFFFFu, v, off);
    return v;
}

// ---------------- K0: prep (u, v, normalized queries) ----------------
__global__ void k_prep(const float* __restrict__ Wih, const float* __restrict__ pW,
                       const float* __restrict__ pb, const float* __restrict__ bih,
                       const float* __restrict__ q) {
    int tid = threadIdx.x;
    if (tid < 384) {
        float su = 0.f, sv = 0.f;
        for (int d = 0; d < 128; d++) {
            float w = Wih[tid * 128 + d];
            su = fmaf(w, pW[d], su);
            sv = fmaf(w, pb[d], sv);
        }
        g_uv[tid] = su;
        g_uv[384 + tid] = sv + bih[tid];
    }
    if (tid < 96) {  // rows of queries: m*32+e
        float ss = 0.f;
        for (int d = 0; d < 128; d++) { float v = q[tid * 128 + d]; ss = fmaf(v, v, ss); }
        float inv = 1.0f / fmaxf(sqrtf(ss), 1e-12f);
        for (int d = 0; d < 128; d++) g_qn[tid * 128 + d] = q[tid * 128 + d] * inv;
    }
}

// ---------------- K1: build s(i,t) from the scrambled [B,T,N,D] reshape + zero Hmix ----
// seq flat elem e = i*64+t maps to hp elem: b=e>>15, t_orig=(e>>9)&63, n_orig=e&511.
// x is [B,N,T,1].
__global__ void k_sfill(const float* __restrict__ x) {
    int e = blockIdx.x * blockDim.x + threadIdx.x;  // 262144 threads
    int b = e >> 15;
    int n_o = e & 511;
    int t_o = (e >> 9) & 63;
    g_s[e] = x[b * 32768 + n_o * 64 + t_o];
    if (e < 8 * 32 * 512) g_Hmix[e] = 0.f;
}

// ---------------- K2: GRU (hot kernel) ----------------
// 128 CTAs x 256 threads, 32 sequences per CTA. W_hh persistent in SMEM as
// Wt[k][d*3+g]. Packed f32x2 FMA inner product.
#define WSTR 388  // padded row stride in floats (1552B, 16B-aligned rows)

__global__ __launch_bounds__(256) void k_gru(const float* __restrict__ Whh,
                                             const float* __restrict__ bhh) {
    extern __shared__ float sm[];
    float* Wt = sm;                    // 128*388
    float* hb = sm + 128 * WSTR;       // h[d][seq], stride 32
    float* ssh = hb + 128 * 32;        // s staged [t][seq]

    const int tid = threadIdx.x;
    const int w = tid >> 5, lane = tid & 31;
    const int sg = lane & 7, dg = lane >> 3;
    const int dbase = (w * 4 + dg) * 4;   // 0..124
    const int i0 = blockIdx.x * 32;

    // stage W_hh transposed + gate-interleaved: Wt[k][d*3+g] = W_hh[g*128+d][k]
    for (int idx = tid; idx < 384 * 128; idx += 256) {
        int o = idx >> 7, k = idx & 127;
        int g = o >> 7, d = o & 127;
        Wt[k * WSTR + d * 3 + g] = Whh[idx];
    }
    for (int idx = tid; idx < 32 * 64; idx += 256) {
        int s = idx >> 6, t = idx & 63;
        ssh[t * 32 + s] = g_s[i0 * 64 + idx];
    }
    for (int idx = tid; idx < 128 * 32; idx += 256) hb[idx] = 0.f;

    float u12[12], v12[12], bh12[12];
#pragma unroll
    for (int l = 0; l < 12; l++) {
        int d = dbase + l / 3, g = l % 3, o = g * 128 + d;
        u12[l] = g_uv[o];
        v12[l] = g_uv[384 + o];
        bh12[l] = bhh[o];
    }
    float hreg[16];
#pragma unroll
    for (int q = 0; q < 16; q++) hreg[q] = 0.f;
    __syncthreads();

    const ulonglong2* wbase = (const ulonglong2*)(Wt + dbase * 3);  // 48B offset, aligned

    for (int t = 0; t < 64; t++) {
        unsigned long long acc[24];
#pragma unroll
        for (int q = 0; q < 24; q++) acc[q] = 0ULL;

        float sv[4];
#pragma unroll
        for (int j = 0; j < 4; j++) sv[j] = ssh[t * 32 + sg * 4 + j];

        const float* hp = hb + sg * 4;
        const ulonglong2* wp = wbase;
#pragma unroll 4
        for (int k = 0; k < 128; k++) {
            unsigned long long a2[4];
#pragma unroll
            for (int j = 0; j < 4; j++) {
                float hv = hp[k * 32 + j];
                a2[j] = pk2(hv, hv);
            }
            ulonglong2 b0 = wp[0], b1 = wp[1], b2 = wp[2];
            unsigned long long bb[6] = {b0.x, b0.y, b1.x, b1.y, b2.x, b2.y};
#pragma unroll
            for (int j = 0; j < 4; j++)
#pragma unroll
                for (int p = 0; p < 6; p++) FMA2(acc[j * 6 + p], a2[j], bb[p]);
            wp += WSTR / 4;
        }

        float hnew[16];
#pragma unroll
        for (int j = 0; j < 4; j++) {
            float gh[12];
#pragma unroll
            for (int p = 0; p < 6; p++) upk2(acc[j * 6 + p], gh[2 * p], gh[2 * p + 1]);
            float s = sv[j];
#pragma unroll
            for (int dd = 0; dd < 4; dd++) {
                int l = dd * 3;
                float gr = gh[l + 0] + bh12[l + 0] + fmaf(s, u12[l + 0], v12[l + 0]);
                float gz = gh[l + 1] + bh12[l + 1] + fmaf(s, u12[l + 1], v12[l + 1]);
                float hn = gh[l + 2] + bh12[l + 2];           // gh_n incl. b_hh
                float gn = fmaf(s, u12[l + 2], v12[l + 2]);   // gi_n
                float r = sigm(gr), z = sigm(gz);
                float ng = tanh_f(fmaf(r, hn, gn));
                float ho = hreg[j * 4 + dd];
                hnew[j * 4 + dd] = fmaf(z, ho - ng, ng);      // (1-z)*ng + z*h
            }
        }
        __syncthreads();
#pragma unroll
        for (int j = 0; j < 4; j++)
#pragma unroll
            for (int dd = 0; dd < 4; dd++) {
                float v = hnew[j * 4 + dd];
                hb[(dbase + dd) * 32 + sg * 4 + j] = v;
                hreg[j * 4 + dd] = v;
            }
        __syncthreads();
    }

    for (int idx = tid; idx < 4096; idx += 256) {
        int s = idx >> 7, d = idx & 127;
        g_H[(i0 + s) * 128 + d] = hb[d * 32 + s];
    }
}

// ---------------- K3: hw = h.out_W, router stats + probs ----------------
__global__ void k_stats(const float* __restrict__ outW, const float* __restrict__ rW,
                        const float* __restrict__ rb, float* __restrict__ dout) {
    int b = blockIdx.x;
    int tid = threadIdx.x, w = tid >> 5, lane = tid & 31;
    __shared__ float mean_s[128], sd_s[128], part[256], lg[3];

    float4 ow = ((const float4*)outW)[lane];
    for (int n = w; n < 512; n += 8) {
        float4 hv = ((const float4*)(g_H + (b * 512 + n) * 128))[lane];
        float acc = hv.x * ow.x + hv.y * ow.y + hv.z * ow.z + hv.w * ow.w;
        acc = warp_sum(acc);
        if (lane == 0) g_hw[b * 512 + n] = acc;
    }

    int d = tid & 127, half = tid >> 7;
    float s0 = 0.f;
    for (int n = half * 256; n < half * 256 + 256; n++) s0 += g_H[(b * 512 + n) * 128 + d];
    part[tid] = s0;
    __syncthreads();
    if (tid < 128) mean_s[tid] = (part[tid] + part[tid + 128]) * (1.0f / 512.0f);
    __syncthreads();
    float mu = mean_s[d];
    float s1 = 0.f;
    for (int n = half * 256; n < half * 256 + 256; n++) {
        float v = g_H[(b * 512 + n) * 128 + d] - mu;
        s1 = fmaf(v, v, s1);
    }
    part[tid] = s1;
    __syncthreads();
    if (tid < 128) sd_s[tid] = sqrtf((part[tid] + part[tid + 128]) * (1.0f / 511.0f));
    __syncthreads();

    if (tid < 3) {
        float a = rb[tid];
        for (int k = 0; k < 128; k++) a = fmaf(mean_s[k], rW[tid * 256 + k], a);
        for (int k = 0; k < 128; k++) a = fmaf(sd_s[k], rW[tid * 256 + 128 + k], a);
        lg[tid] = a;
    }
    __syncthreads();
    if (tid == 0) {
        float mx = fmaxf(lg[0], fmaxf(lg[1], lg[2]));
        float e0 = __expf(lg[0] - mx), e1 = __expf(lg[1] - mx), e2 = __expf(lg[2] - mx);
        float inv = 1.0f / (e0 + e1 + e2);
        g_probs[b * 3 + 0] = e0 * inv;
        g_probs[b * 3 + 1] = e1 * inv;
        g_probs[b * 3 + 2] = e2 * inv;
        dout[4096 + b * 3 + 0] = e0 * inv;
        dout[4096 + b * 3 + 1] = e1 * inv;
        dout[4096 + b * 3 + 2] = e2 * inv;
    }
}

// ---------------- K_prior: zpw[b,n] = sum_j prior[n,j]*hw[b,j] ----------------
__global__ void k_prior(const float* __restrict__ prior) {
    __shared__ float prow[512];
    __shared__ float red[8][8];  // [warp][b]
    int n = blockIdx.x, tid = threadIdx.x, w = tid >> 5, lane = tid & 31;
    for (int j = tid; j < 512; j += 256) prow[j] = prior[n * 512 + j];
    __syncthreads();
    int j0 = tid * 2;
    float p0 = prow[j0], p1 = prow[j0 + 1];
#pragma unroll
    for (int b = 0; b < 8; b++) {
        float acc = p0 * g_hw[b * 512 + j0] + p1 * g_hw[b * 512 + j0 + 1];
        acc = warp_sum(acc);
        if (lane == 0) red[w][b] = acc;
    }
    __syncthreads();
    if (tid < 8) {
        float s = 0.f;
#pragma unroll
        for (int ww = 0; ww < 8; ww++) s += red[ww][tid];
        g_zpw[tid * 512 + n] = s;
    }
}

// ---------------- K4: scores[b,m,e,n] = norm(h@spW[m]^T + spb[m]) . qn[m,e] --------
// grid = B*M*16 blocks; each block: one (b,m), 32 n.
__global__ __launch_bounds__(256) void k_scores(const float* __restrict__ spW,
                                                const float* __restrict__ spb) {
    extern __shared__ float sm4[];
    float* W_s = sm4;                    // [128][129]
    float* qn_s = W_s + 128 * 129;       // [k][e] : 128*32
    float* h_s = qn_s + 128 * 32;        // [32][128]
    float* sb_s = h_s + 32 * 128;        // [128]
    float* hs_s = sb_s + 128;            // [8 warps][128]

    int bx = blockIdx.x;
    int b = bx / 48, rem = bx % 48;
    int m = rem / 16, n0 = (rem % 16) * 32;
    int tid = threadIdx.x, w = tid >> 5, lane = tid & 31;

    for (int idx = tid; idx < 16384; idx += 256) {
        int k = idx >> 7, d = idx & 127;
        W_s[k * 129 + d] = spW[m * 16384 + idx];
    }
    for (int idx = tid; idx < 4096; idx += 256) {
        int e = idx >> 7, d = idx & 127;
        qn_s[d * 32 + e] = g_qn[m * 4096 + idx];
    }
    for (int idx = tid; idx < 32 * 128; idx += 256)
        h_s[idx] = g_H[(b * 512 + n0) * 128 + idx];
    if (tid < 128) sb_s[tid] = spb[m * 128 + tid];
    __syncthreads();

    for (int nn = w; nn < 32; nn += 8) {
        const float* hrow = h_s + nn * 128;
        float hsk[4];
#pragma unroll
        for (int q = 0; q < 4; q++) hsk[q] = sb_s[lane + 32 * q];
        for (int d = 0; d < 128; d++) {
            float hv = hrow[d];
#pragma unroll
            for (int q = 0; q < 4; q++)
                hsk[q] = fmaf(W_s[(lane + 32 * q) * 129 + d], hv, hsk[q]);
        }
        float sq = hsk[0] * hsk[0] + hsk[1] * hsk[1] + hsk[2] * hsk[2] + hsk[3] * hsk[3];
        sq = warp_sum(sq);
        float inv = 1.0f / fmaxf(sqrtf(sq), 1e-12f);
#pragma unroll
        for (int q = 0; q < 4; q++) hs_s[w * 128 + lane + 32 * q] = hsk[q] * inv;
        __syncwarp();

        float acc = 0.f;
        for (int k = 0; k < 128; k++)
            acc = fmaf(hs_s[w * 128 + k], qn_s[k * 32 + lane], acc);
        g_scores[((b * 3 + m) * 32 + lane) * 512 + n0 + nn] = acc;
        __syncwarp();
    }
}

// ---------------- K5: top-25 over n + softmax(T=0.7) + Hmix accumulation ----------
__global__ void k_topk() {
    int tid = threadIdx.x, w = tid >> 5, lane = tid & 31;
    int row = blockIdx.x * 8 + w;         // 768 rows = [b][m][e]
    int b = row / 96, m = (row / 32) % 3, e = row % 32;
    const float* sc = g_scores + row * 512;

    float v[16];
#pragma unroll
    for (int j = 0; j < 16; j++) v[j] = sc[lane + j * 32];

    float topv[KTOP];
    int topi[KTOP];
    for (int it = 0; it < KTOP; it++) {
        float bv = -FLT_MAX;
        int bi = 0x7FFFFFFF;
#pragma unroll
        for (int j = 0; j < 16; j++) {
            if (v[j] > bv) { bv = v[j]; bi = lane + j * 32; }
        }
#pragma unroll
        for (int off = 16; off; off >>= 1) {
            float ov = __shfl_xor_sync(0xFFFFFFFFu, bv, off);
            int oi = __shfl_xor_sync(0xFFFFFFFFu, bi, off);
            if (ov > bv || (ov == bv && oi < bi)) { bv = ov; bi = oi; }
        }
        topv[it] = bv;
        topi[it] = bi;
#pragma unroll
        for (int j = 0; j < 16; j++)
            if (lane + j * 32 == bi) v[j] = -FLT_MAX;
    }

    if (lane == 0) {
        float vmax = topv[0];
        float ssum = 0.f;
        float wexp[KTOP];
        const float itau = 1.0f / 0.7f;
        for (int i = 0; i < KTOP; i++) {
            wexp[i] = __expf((topv[i] - vmax) * itau);
            ssum += wexp[i];
        }
        float pm = g_probs[b * 3 + m] / ssum;
        float* hm = g_Hmix + (b * 32 + e) * 512;
        for (int i = 0; i < KTOP; i++) atomicAdd(&hm[topi[i]], pm * wexp[i]);
    }
}

// ---------------- K6: ew = Hmix@hw ; out = a*zpw + (1-a)*Hmix^T@ew + out_b --------
__global__ void k_final(const float* __restrict__ plog, const float* __restrict__ outb,
                        float* __restrict__ dout) {
    int b = blockIdx.x, tid = threadIdx.x, w = tid >> 5, lane = tid & 31;
    __shared__ float hwsm[512], ewsm[32];
    for (int j = tid; j < 512; j += 256) hwsm[j] = g_hw[b * 512 + j];
    __syncthreads();
#pragma unroll
    for (int ei = 0; ei < 4; ei++) {
        int e = w + ei * 8;
        float acc = 0.f;
        const float* hm = g_Hmix + (b * 32 + e) * 512;
        for (int n = lane; n < 512; n += 32) acc = fmaf(hm[n], hwsm[n], acc);
        acc = warp_sum(acc);
        if (lane == 0) ewsm[e] = acc;
    }
    __syncthreads();
    float alpha = sigm(plog[0]);
    float ob = outb[0];
    for (int n = tid; n < 512; n += 256) {
        float acc = 0.f;
#pragma unroll 8
        for (int e = 0; e < 32; e++)
            acc = fmaf(g_Hmix[(b * 32 + e) * 512 + n], ewsm[e], acc);
        dout[b * 512 + n] = fmaf(alpha, g_zpw[b * 512 + n] - acc, acc) + ob;
    }
}

// ---------------- launch ----------------
extern "C" void kernel_launch(void* const* d_in, const int* in_sizes, int n_in,
                              void* d_out, int out_size) {
    const float* x     = (const float*)d_in[0];
    const float* prior = (const float*)d_in[1];
    const float* pW    = (const float*)d_in[2];
    const float* pb    = (const float*)d_in[3];
    const float* Wih   = (const float*)d_in[4];
    const float* Whh   = (const float*)d_in[5];
    const float* bih   = (const float*)d_in[6];
    const float* bhh   = (const float*)d_in[7];
    const float* spW   = (const float*)d_in[8];
    const float* spb   = (const float*)d_in[9];
    const float* rW    = (const float*)d_in[10];
    const float* rb    = (const float*)d_in[11];
    const float* outW  = (const float*)d_in[12];
    const float* outb  = (const float*)d_in[13];
    const float* plog  = (const float*)d_in[14];
    const float* q     = (const float*)d_in[15];
    float* dout = (float*)d_out;

    const int smem_gru = (128 * WSTR + 128 * 32 + 32 * 64) * (int)sizeof(float);   // 223232 B
    const int smem_sc  = (128 * 129 + 128 * 32 + 32 * 128 + 128 + 8 * 128) * (int)sizeof(float);
    cudaFuncSetAttribute(k_gru, cudaFuncAttributeMaxDynamicSharedMemorySize, smem_gru);
    cudaFuncSetAttribute(k_scores, cudaFuncAttributeMaxDynamicSharedMemorySize, smem_sc);

    k_prep<<<1, 384>>>(Wih, pW, pb, bih, q);
    k_sfill<<<1024, 256>>>(x);
    k_gru<<<128, 256, smem_gru>>>(Whh, bhh);
    k_stats<<<8, 256>>>(outW, rW, rb, dout);
    k_prior<<<512, 256>>>(prior);
    k_scores<<<384, 256, smem_sc>>>(spW, spb);
    k_topk<<<96, 256>>>();
    k_final<<<8, 256>>>(plog, outb, dout);
}

// round 11
// speedup vs baseline: 1.2306x; 1.2291x over previous
#include <cuda_runtime.h>
#include <math.h>
#include <float.h>

// Shapes: B=8, N=512, T=64, D=128, E=32, M=3, k_top=25
#define KTOP 25

// ---------------- scratch (__device__ globals; allocation is forbidden) ----------------
__device__ float g_uv[2 * 384];            // u = W_ih@proj_W ; v = W_ih@proj_b + b_ih
__device__ float g_qn[3 * 32 * 128];       // normalized queries [m][e][d]
__device__ float g_H[4096 * 128];          // final GRU hidden state [b*512+n][d]
__device__ float g_hw[4096];               // h . out_W
__device__ float g_zpw[4096];              // prior @ hw
__device__ float g_part[8 * 16 * 256];     // per-(b,chunk) partial [sum(128) | sumsq(128)]
__device__ float g_probs[8 * 3];
__device__ float g_scores[8 * 3 * 32 * 512];   // [b][m][e][n]
__device__ float g_Hmix[8 * 32 * 512];         // [b][e][n]

// ---------------- helpers ----------------
__device__ __forceinline__ unsigned long long pk2(float lo, float hi) {
    unsigned long long r;
    asm("mov.b64 %0,{%1,%2};" : "=l"(r) : "f"(lo), "f"(hi));
    return r;
}
__device__ __forceinline__ void upk2(unsigned long long v, float& lo, float& hi) {
    asm("mov.b64 {%0,%1},%2;" : "=f"(lo), "=f"(hi) : "l"(v));
}
#define FMA2(acc, a, b) asm("fma.rn.f32x2 %0,%1,%2,%0;" : "+l"(acc) : "l"(a), "l"(b))

__device__ __forceinline__ float sigm(float x) { return 1.0f / (1.0f + __expf(-x)); }
__device__ __forceinline__ float tanh_f(float x) {
    float t = __expf(-2.0f * x);
    return (1.0f - t) / (1.0f + t);
}
__device__ __forceinline__ float warp_sum(float v) {
#pragma unroll
    for (int off = 16; off; off >>= 1) v += __shfl_xor_sync(0xFFFFFFFFu, v, off);
    return v;
}

// ---------------- K0a: u = W_ih@proj_W, v = W_ih@proj_b + b_ih ----------------
__global__ void k_prep_uv(const float* __restrict__ Wih, const float* __restrict__ pW,
                          const float* __restrict__ pb, const float* __restrict__ bih) {
    int tid = threadIdx.x;
    if (tid < 384) {
        float su = 0.f, sv = 0.f;
        for (int d = 0; d < 128; d++) {
            float w = Wih[tid * 128 + d];
            su = fmaf(w, pW[d], su);
            sv = fmaf(w, pb[d], sv);
        }
        g_uv[tid] = su;
        g_uv[384 + tid] = sv + bih[tid];
    }
}

// ---------------- K0b: normalize queries (warp per row, 96 rows) ----------------
__global__ void k_prep_q(const float* __restrict__ q) {
    int w = threadIdx.x >> 5, lane = threadIdx.x & 31;
#pragma unroll
    for (int rr = 0; rr < 4; rr++) {
        int row = (blockIdx.x * 8 + w) * 4 + rr;  // 0..95
        float4 v = ((const float4*)(q + row * 128))[lane];
        float ss = v.x * v.x + v.y * v.y + v.z * v.z + v.w * v.w;
        ss = warp_sum(ss);
        float inv = 1.0f / fmaxf(sqrtf(ss), 1e-12f);
        float4 o = make_float4(v.x * inv, v.y * inv, v.z * inv, v.w * inv);
        ((float4*)(g_qn + row * 128))[lane] = o;
    }
}

// ---------------- K0c: zero Hmix ----------------
__global__ void k_zero() {
    int base = blockIdx.x * 256 + threadIdx.x;  // grid 128 x 256 = 32768
#pragma unroll
    for (int i = 0; i < 4; i++) g_Hmix[base + i * 32768] = 0.f;
}

// ---------------- K1: GRU (hot kernel) ----------------
// 128 CTAs x 512 threads, 32 sequences per CTA. W_hh persistent in SMEM as
// Wt[k][d*3+g] (gate-interleaved). Packed f32x2 FMA inner product.
// Thread -> (seq-pair sp = lane&15, dtile = w*2 + (lane>>4)).
#define WSTR 388  // padded row stride in floats (1552B, 16B-aligned rows)

__global__ __launch_bounds__(512) void k_gru(const float* __restrict__ Whh,
                                             const float* __restrict__ bhh,
                                             const float* __restrict__ x) {
    extern __shared__ float sm[];
    float* Wt = sm;                    // 128*388
    float* hb = sm + 128 * WSTR;       // h[d][seq], stride 32
    float* ssh = hb + 128 * 32;        // s staged [t][seq] : 64*32

    const int tid = threadIdx.x;
    const int w = tid >> 5, lane = tid & 31;
    const int sp = lane & 15;                 // seq pair id (seqs 2sp, 2sp+1)
    const int dtile = w * 2 + (lane >> 4);    // 0..31
    const int dbase = dtile * 4;              // 0..124
    const int i0 = blockIdx.x * 32;

    // stage W_hh transposed + gate-interleaved: Wt[k][d*3+g] = W_hh[g*128+d][k]
    for (int idx = tid; idx < 384 * 128; idx += 512) {
        int o = idx >> 7, k = idx & 127;
        int g = o >> 7, d = o & 127;
        Wt[k * WSTR + d * 3 + g] = Whh[idx];
    }
    // gather the scalar input directly from x via the scrambled-reshape map:
    // s(i,t) = x[(i>>9)*32768 + ((i&7)*64 + t)*64 + ((i>>3)&63)]
    for (int idx = tid; idx < 2048; idx += 512) {
        int ss = idx >> 6, t = idx & 63;
        int i = i0 + ss;
        ssh[t * 32 + ss] = x[(i >> 9) * 32768 + ((i & 7) * 64 + t) * 64 + ((i >> 3) & 63)];
    }
    for (int idx = tid; idx < 128 * 32; idx += 512) hb[idx] = 0.f;

    float u12[12], v12[12], bh12[12];
#pragma unroll
    for (int l = 0; l < 12; l++) {
        int d = dbase + l / 3, g = l % 3, o = g * 128 + d;
        u12[l] = g_uv[o];
        v12[l] = g_uv[384 + o];
        bh12[l] = bhh[o];
    }
    float hreg[8];
#pragma unroll
    for (int q = 0; q < 8; q++) hreg[q] = 0.f;
    __syncthreads();

    const ulonglong2* wbase = (const ulonglong2*)(Wt + dbase * 3);  // 48B-multiple offset
    const float2* hpb = ((const float2*)hb) + sp;

    for (int t = 0; t < 64; t++) {
        unsigned long long acc[12];
#pragma unroll
        for (int q = 0; q < 12; q++) acc[q] = 0ULL;

        float sv0 = ssh[t * 32 + sp * 2];
        float sv1 = ssh[t * 32 + sp * 2 + 1];

        const ulonglong2* wp = wbase;
#pragma unroll 4
        for (int k = 0; k < 128; k++) {
            float2 hv = hpb[k * 16];
            unsigned long long a0 = pk2(hv.x, hv.x);
            unsigned long long a1 = pk2(hv.y, hv.y);
            ulonglong2 b0 = wp[0], b1 = wp[1], b2 = wp[2];
            unsigned long long bb[6] = {b0.x, b0.y, b1.x, b1.y, b2.x, b2.y};
#pragma unroll
            for (int p = 0; p < 6; p++) {
                FMA2(acc[p], a0, bb[p]);
                FMA2(acc[6 + p], a1, bb[p]);
            }
            wp += WSTR / 4;
        }

        float hnew[8];
#pragma unroll
        for (int j = 0; j < 2; j++) {
            float gh[12];
#pragma unroll
            for (int p = 0; p < 6; p++) upk2(acc[j * 6 + p], gh[2 * p], gh[2 * p + 1]);
            float s = j ? sv1 : sv0;
#pragma unroll
            for (int dd = 0; dd < 4; dd++) {
                int l = dd * 3;
                float gr = gh[l + 0] + bh12[l + 0] + fmaf(s, u12[l + 0], v12[l + 0]);
                float gz = gh[l + 1] + bh12[l + 1] + fmaf(s, u12[l + 1], v12[l + 1]);
                float hn = gh[l + 2] + bh12[l + 2];           // gh_n incl. b_hh
                float gn = fmaf(s, u12[l + 2], v12[l + 2]);   // gi_n
                float r = sigm(gr), z = sigm(gz);
                float ng = tanh_f(fmaf(r, hn, gn));
                float ho = hreg[j * 4 + dd];
                hnew[j * 4 + dd] = fmaf(z, ho - ng, ng);      // (1-z)*ng + z*h
            }
        }
        __syncthreads();
#pragma unroll
        for (int dd = 0; dd < 4; dd++) {
            float2 o = make_float2(hnew[dd], hnew[4 + dd]);
            *((float2*)(hb + (dbase + dd) * 32) + sp) = o;
            hreg[dd] = o.x;
            hreg[4 + dd] = o.y;
        }
        __syncthreads();
    }

    for (int idx = tid; idx < 4096; idx += 512) {
        int s = idx >> 7, d = idx & 127;
        g_H[(i0 + s) * 128 + d] = hb[d * 32 + s];
    }
}

// ---------------- K2: hw = h.out_W + partial router stats (grid 8x16) ----------------
__global__ void k_hw_stats(const float* __restrict__ outW) {
    int b = blockIdx.x >> 4, c = blockIdx.x & 15;
    int n0 = c * 32;
    int tid = threadIdx.x, w = tid >> 5, lane = tid & 31;
    __shared__ float ps0[256], ps1[256];

    float4 ow = ((const float4*)outW)[lane];
#pragma unroll
    for (int p = 0; p < 4; p++) {
        int n = n0 + w + 8 * p;
        float4 hv = ((const float4*)(g_H + (b * 512 + n) * 128))[lane];
        float acc = hv.x * ow.x + hv.y * ow.y + hv.z * ow.z + hv.w * ow.w;
        acc = warp_sum(acc);
        if (lane == 0) g_hw[b * 512 + n] = acc;
    }

    int d = tid & 127, half = tid >> 7;
    float s0 = 0.f, s1 = 0.f;
    for (int nn = half * 16; nn < half * 16 + 16; nn++) {
        float v = g_H[(b * 512 + n0 + nn) * 128 + d];
        s0 += v;
        s1 = fmaf(v, v, s1);
    }
    ps0[tid] = s0;
    ps1[tid] = s1;
    __syncthreads();
    if (tid < 128) {
        g_part[(b * 16 + c) * 256 + tid] = ps0[tid] + ps0[tid + 128];
        g_part[(b * 16 + c) * 256 + 128 + tid] = ps1[tid] + ps1[tid + 128];
    }
}

// ---------------- K3: router probs from partials (grid 8) ----------------
__global__ void k_router(const float* __restrict__ rW, const float* __restrict__ rb,
                         float* __restrict__ dout) {
    int b = blockIdx.x, tid = threadIdx.x;
    __shared__ float mean_s[128], sd_s[128], lg[3];
    {
        int d = tid & 127, which = tid >> 7;
        float s = 0.f;
        for (int c = 0; c < 16; c++) s += g_part[(b * 16 + c) * 256 + which * 128 + d];
        if (which == 0) mean_s[d] = s * (1.0f / 512.0f);
        else sd_s[d] = s;  // sumsq (temp)
    }
    __syncthreads();
    if (tid < 128) {
        float mu = mean_s[tid];
        float var = (sd_s[tid] - 512.0f * mu * mu) * (1.0f / 511.0f);
        sd_s[tid] = sqrtf(fmaxf(var, 0.f));
    }
    __syncthreads();
    if (tid < 3) {
        float a = rb[tid];
        for (int k = 0; k < 128; k++) a = fmaf(mean_s[k], rW[tid * 256 + k], a);
        for (int k = 0; k < 128; k++) a = fmaf(sd_s[k], rW[tid * 256 + 128 + k], a);
        lg[tid] = a;
    }
    __syncthreads();
    if (tid == 0) {
        float mx = fmaxf(lg[0], fmaxf(lg[1], lg[2]));
        float e0 = __expf(lg[0] - mx), e1 = __expf(lg[1] - mx), e2 = __expf(lg[2] - mx);
        float inv = 1.0f / (e0 + e1 + e2);
        g_probs[b * 3 + 0] = e0 * inv;
        g_probs[b * 3 + 1] = e1 * inv;
        g_probs[b * 3 + 2] = e2 * inv;
        dout[4096 + b * 3 + 0] = e0 * inv;
        dout[4096 + b * 3 + 1] = e1 * inv;
        dout[4096 + b * 3 + 2] = e2 * inv;
    }
}

// ---------------- K4: zpw[b,n] = sum_j prior[n,j]*hw[b,j] (grid 512) ----------------
__global__ void k_prior(const float* __restrict__ prior) {
    __shared__ float prow[512];
    __shared__ float red[8][8];  // [warp][b]
    int n = blockIdx.x, tid = threadIdx.x, w = tid >> 5, lane = tid & 31;
    for (int j = tid; j < 512; j += 256) prow[j] = prior[n * 512 + j];
    __syncthreads();
    int j0 = tid * 2;
    float p0 = prow[j0], p1 = prow[j0 + 1];
#pragma unroll
    for (int b = 0; b < 8; b++) {
        float acc = p0 * g_hw[b * 512 + j0] + p1 * g_hw[b * 512 + j0 + 1];
        acc = warp_sum(acc);
        if (lane == 0) red[w][b] = acc;
    }
    __syncthreads();
    if (tid < 8) {
        float s = 0.f;
#pragma unroll
        for (int ww = 0; ww < 8; ww++) s += red[ww][tid];
        g_zpw[tid * 512 + n] = s;
    }
}

// ---------------- K5: scores[b,m,e,n] = norm(h@spW[m]^T + spb[m]) . qn[m,e] --------
// grid = B*M*16 blocks; each block: one (b,m), 32 n.
__global__ __launch_bounds__(256) void k_scores(const float* __restrict__ spW,
                                                const float* __restrict__ spb) {
    extern __shared__ float sm4[];
    float* W_s = sm4;                    // [128][129]
    float* qn_s = W_s + 128 * 129;       // [k][e] : 128*32
    float* h_s = qn_s + 128 * 32;        // [32][128]
    float* sb_s = h_s + 32 * 128;        // [128]
    float* hs_s = sb_s + 128;            // [8 warps][128]

    int bx = blockIdx.x;
    int b = bx / 48, rem = bx % 48;
    int m = rem / 16, n0 = (rem % 16) * 32;
    int tid = threadIdx.x, w = tid >> 5, lane = tid & 31;

    for (int idx = tid; idx < 16384; idx += 256) {
        int k = idx >> 7, d = idx & 127;
        W_s[k * 129 + d] = spW[m * 16384 + idx];
    }
    for (int idx = tid; idx < 4096; idx += 256) {
        int e = idx >> 7, d = idx & 127;
        qn_s[d * 32 + e] = g_qn[m * 4096 + idx];
    }
    for (int idx = tid; idx < 32 * 128; idx += 256)
        h_s[idx] = g_H[(b * 512 + n0) * 128 + idx];
    if (tid < 128) sb_s[tid] = spb[m * 128 + tid];
    __syncthreads();

    for (int nn = w; nn < 32; nn += 8) {
        const float* hrow = h_s + nn * 128;
        float hsk[4];
#pragma unroll
        for (int q = 0; q < 4; q++) hsk[q] = sb_s[lane + 32 * q];
        for (int d = 0; d < 128; d++) {
            float hv = hrow[d];
#pragma unroll
            for (int q = 0; q < 4; q++)
                hsk[q] = fmaf(W_s[(lane + 32 * q) * 129 + d], hv, hsk[q]);
        }
        float sq = hsk[0] * hsk[0] + hsk[1] * hsk[1] + hsk[2] * hsk[2] + hsk[3] * hsk[3];
        sq = warp_sum(sq);
        float inv = 1.0f / fmaxf(sqrtf(sq), 1e-12f);
#pragma unroll
        for (int q = 0; q < 4; q++) hs_s[w * 128 + lane + 32 * q] = hsk[q] * inv;
        __syncwarp();

        float acc = 0.f;
        for (int k = 0; k < 128; k++)
            acc = fmaf(hs_s[w * 128 + k], qn_s[k * 32 + lane], acc);
        g_scores[((b * 3 + m) * 32 + lane) * 512 + n0 + nn] = acc;
        __syncwarp();
    }
}

// ---------------- K6: top-25 over n + softmax(T=0.7) + Hmix accumulation ----------
__global__ void k_topk() {
    int tid = threadIdx.x, w = tid >> 5, lane = tid & 31;
    int row = blockIdx.x * 8 + w;         // 768 rows = [b][m][e]
    int b = row / 96, m = (row / 32) % 3, e = row % 32;
    const float* sc = g_scores + row * 512;

    float v[16];
#pragma unroll
    for (int j = 0; j < 16; j++) v[j] = sc[lane + j * 32];

    float topv[KTOP];
    int topi[KTOP];
    for (int it = 0; it < KTOP; it++) {
        float bv = -FLT_MAX;
        int bi = 0x7FFFFFFF;
#pragma unroll
        for (int j = 0; j < 16; j++) {
            if (v[j] > bv) { bv = v[j]; bi = lane + j * 32; }
        }
#pragma unroll
        for (int off = 16; off; off >>= 1) {
            float ov = __shfl_xor_sync(0xFFFFFFFFu, bv, off);
            int oi = __shfl_xor_sync(0xFFFFFFFFu, bi, off);
            if (ov > bv || (ov == bv && oi < bi)) { bv = ov; bi = oi; }
        }
        topv[it] = bv;
        topi[it] = bi;
#pragma unroll
        for (int j = 0; j < 16; j++)
            if (lane + j * 32 == bi) v[j] = -FLT_MAX;
    }

    if (lane == 0) {
        float vmax = topv[0];
        float ssum = 0.f;
        float wexp[KTOP];
        const float itau = 1.0f / 0.7f;
        for (int i = 0; i < KTOP; i++) {
            wexp[i] = __expf((topv[i] - vmax) * itau);
            ssum += wexp[i];
        }
        float pm = g_probs[b * 3 + m] / ssum;
        float* hm = g_Hmix + (b * 32 + e) * 512;
        for (int i = 0; i < KTOP; i++) atomicAdd(&hm[topi[i]], pm * wexp[i]);
    }
}

// ---------------- K7: ew = Hmix@hw ; out = a*zpw + (1-a)*Hmix^T@ew + out_b --------
__global__ void k_final(const float* __restrict__ plog, const float* __restrict__ outb,
                        float* __restrict__ dout) {
    int b = blockIdx.x, tid = threadIdx.x, w = tid >> 5, lane = tid & 31;
    __shared__ float hwsm[512], ewsm[32];
    for (int j = tid; j < 512; j += 256) hwsm[j] = g_hw[b * 512 + j];
    __syncthreads();
#pragma unroll
    for (int ei = 0; ei < 4; ei++) {
        int e = w + ei * 8;
        float acc = 0.f;
        const float* hm = g_Hmix + (b * 32 + e) * 512;
        for (int n = lane; n < 512; n += 32) acc = fmaf(hm[n], hwsm[n], acc);
        acc = warp_sum(acc);
        if (lane == 0) ewsm[e] = acc;
    }
    __syncthreads();
    float alpha = sigm(plog[0]);
    float ob = outb[0];
    for (int n = tid; n < 512; n += 256) {
        float acc = 0.f;
#pragma unroll 8
        for (int e = 0; e < 32; e++)
            acc = fmaf(g_Hmix[(b * 32 + e) * 512 + n], ewsm[e], acc);
        dout[b * 512 + n] = fmaf(alpha, g_zpw[b * 512 + n] - acc, acc) + ob;
    }
}

// ---------------- launch ----------------
extern "C" void kernel_launch(void* const* d_in, const int* in_sizes, int n_in,
                              void* d_out, int out_size) {
    const float* x     = (const float*)d_in[0];
    const float* prior = (const float*)d_in[1];
    const float* pW    = (const float*)d_in[2];
    const float* pb    = (const float*)d_in[3];
    const float* Wih   = (const float*)d_in[4];
    const float* Whh   = (const float*)d_in[5];
    const float* bih   = (const float*)d_in[6];
    const float* bhh   = (const float*)d_in[7];
    const float* spW   = (const float*)d_in[8];
    const float* spb   = (const float*)d_in[9];
    const float* rW    = (const float*)d_in[10];
    const float* rb    = (const float*)d_in[11];
    const float* outW  = (const float*)d_in[12];
    const float* outb  = (const float*)d_in[13];
    const float* plog  = (const float*)d_in[14];
    const float* q     = (const float*)d_in[15];
    float* dout = (float*)d_out;

    const int smem_gru = (128 * WSTR + 128 * 32 + 64 * 32) * (int)sizeof(float);   // 223232 B
    const int smem_sc  = (128 * 129 + 128 * 32 + 32 * 128 + 128 + 8 * 128) * (int)sizeof(float);
    cudaFuncSetAttribute(k_gru, cudaFuncAttributeMaxDynamicSharedMemorySize, smem_gru);
    cudaFuncSetAttribute(k_scores, cudaFuncAttributeMaxDynamicSharedMemorySize, smem_sc);

    k_prep_uv<<<1, 384>>>(Wih, pW, pb, bih);        // idx 0
    k_prep_q<<<3, 256>>>(q);                        // idx 1
    k_zero<<<128, 256>>>();                         // idx 2
    k_gru<<<128, 512, smem_gru>>>(Whh, bhh, x);     // idx 3  (profile target)
    k_hw_stats<<<128, 256>>>(outW);                 // idx 4
    k_router<<<8, 256>>>(rW, rb, dout);             // idx 5
    k_prior<<<512, 256>>>(prior);                   // idx 6
    k_scores<<<384, 256, smem_sc>>>(spW, spb);      // idx 7
    k_topk<<<96, 256>>>();                          // idx 8
    k_final<<<8, 256>>>(plog, outb, dout);          // idx 9
}